// round 8
// baseline (speedup 1.0000x reference)
#include <cuda_runtime.h>
#include <math_constants.h>
#include <cstdint>

#define BB 128
#define TT 2048
#define HH 256
#define OUTD 128

#define CHUNK_ROWS 128
#define NCHUNK 16                             // chunks per batch
#define NCHUNKS_TOTAL (BB * NCHUNK)           // 2048
#define NPART NCHUNKS_TOTAL

#define STAGE_ROWS 16
#define STAGE_BYTES (STAGE_ROWS * HH * 4)     // 16384
#define NSTAGE 5
#define STAGES_PER_CHUNK (CHUNK_ROWS / STAGE_ROWS)  // 8

#define NCONS 4                               // consumer warps
#define K1_THREADS 160                        // 128 consumer + 32 producer
#define PROD_TID 128
#define K1_GRID 296                           // 148 SMs x 2 CTAs (persistent)

// dynamic smem layout (bytes)
#define OFF_TILES 0
#define SZ_TILES  (NSTAGE * STAGE_BYTES)      // 81920
#define OFF_ACC   (OFF_TILES + SZ_TILES)
#define SZ_ACC    (NCONS * HH * 4)            // 4096
#define OFF_WM    (OFF_ACC + SZ_ACC)          // 86016
#define OFF_WZ    (OFF_WM + 16)
#define OFF_BARS  (OFF_WZ + 16)               // 86048, 8-aligned
#define SMEM_K1   (OFF_BARS + 2 * NSTAGE * 8) // 86128 -> 2 CTAs/SM

// Global scratch (allocation-free)
__device__ float g_v[BB * HH];
__device__ float g_m[NPART];
__device__ float g_z[NPART];
__device__ float g_acc[NPART * HH];

// ---------------- PTX helpers ----------------
__device__ __forceinline__ uint32_t s2u(const void* p) {
    uint32_t a;
    asm("{ .reg .u64 t; cvta.to.shared.u64 t, %1; cvt.u32.u64 %0, t; }"
        : "=r"(a) : "l"(p));
    return a;
}
__device__ __forceinline__ void mbar_init(uint32_t bar, uint32_t cnt) {
    asm volatile("mbarrier.init.shared.b64 [%0], %1;" :: "r"(bar), "r"(cnt) : "memory");
}
__device__ __forceinline__ void mbar_expect_tx(uint32_t bar, uint32_t bytes) {
    asm volatile("mbarrier.arrive.expect_tx.shared.b64 _, [%0], %1;"
                 :: "r"(bar), "r"(bytes) : "memory");
}
__device__ __forceinline__ void mbar_arrive(uint32_t bar) {
    asm volatile("mbarrier.arrive.release.cta.shared.b64 _, [%0];" :: "r"(bar) : "memory");
}
__device__ __forceinline__ void mbar_wait(uint32_t bar, uint32_t parity) {
    uint32_t done;
    asm volatile(
        "{ .reg .pred p; mbarrier.try_wait.parity.acquire.cta.shared::cta.b64 p, [%1], %2; "
        "selp.b32 %0, 1, 0, p; }" : "=r"(done) : "r"(bar), "r"(parity) : "memory");
    while (!done) {
        asm volatile(
            "{ .reg .pred p; mbarrier.try_wait.parity.acquire.cta.shared::cta.b64 p, [%1], %2, 0x989680; "
            "selp.b32 %0, 1, 0, p; }" : "=r"(done) : "r"(bar), "r"(parity) : "memory");
    }
}
__device__ __forceinline__ void bulk_copy_g2s(uint32_t dst_smem, const void* src,
                                              uint32_t bytes, uint32_t mbar) {
    asm volatile(
        "cp.async.bulk.shared::cta.global.mbarrier::complete_tx::bytes [%0], [%1], %2, [%3];"
        :: "r"(dst_smem), "l"(src), "r"(bytes), "r"(mbar) : "memory");
}
__device__ __forceinline__ void fence_async_shared() {
    asm volatile("fence.proxy.async.shared::cta;" ::: "memory");
}
__device__ __forceinline__ void bar_cons() {          // 4 consumer warps only
    asm volatile("bar.sync 1, 128;" ::: "memory");
}

// ---------------------------------------------------------------------------
// kernel0: V[b,h] = sum_k W_score[h,k]*ht[b,k].  grid=(16,32)=512 CTAs,
//          128 thr, tile 8b x 8h, split-K by 2 with shfl combine.
// ---------------------------------------------------------------------------
#define K0_PAD 260

__global__ __launch_bounds__(128)
void k0_compute_v(const float* __restrict__ hidden,
                  const float* __restrict__ Wscore)
{
    __shared__ float sW [8][K0_PAD];
    __shared__ float sHt[8][K0_PAD];

    const int b0 = blockIdx.x * 8;
    const int h0 = blockIdx.y * 8;
    const int tid = threadIdx.x;

    // cooperative loads: 16 rows (8 W + 8 ht) x 256 floats, 8 float4/thread
    {
        const int row = tid >> 3, seg = (tid & 7) * 32;
        const float* src = (row < 8)
            ? Wscore + (size_t)(h0 + row) * HH + seg
            : hidden + ((size_t)(b0 + row - 8) * TT + (TT - 1)) * HH + seg;
        float* dst = (row < 8) ? &sW[row][seg] : &sHt[row - 8][seg];
        #pragma unroll
        for (int u = 0; u < 8; u++)
            *(float4*)(dst + u * 4) = *(const float4*)(src + u * 4);
    }
    __syncthreads();

    // thread: h = tid>>4, b = (tid>>1)&7, half = tid&1 covers 128 channels
    const int h = tid >> 4, b = (tid >> 1) & 7, half = tid & 1;
    const float* wr = &sW[h][half * 128];
    const float* hr = &sHt[b][half * 128];
    float acc = 0.f;
    #pragma unroll 8
    for (int k = 0; k < 128; k += 4) {
        const float4 wv = *(const float4*)(wr + k);
        const float4 hv = *(const float4*)(hr + k);
        acc += wv.x * hv.x + wv.y * hv.y + wv.z * hv.z + wv.w * hv.w;
    }
    acc += __shfl_xor_sync(0xffffffffu, acc, 1);
    if (half == 0) g_v[(b0 + b) * HH + h0 + h] = acc;
}

// ---------------------------------------------------------------------------
// kernel1: persistent warp-specialized streamer.
//          296 CTAs x 160 thr: 1 producer warp (16KB bulk copies, 5-stage
//          ring), 4 consumer warps (online softmax partials per 128-row chunk)
// ---------------------------------------------------------------------------
__global__ __launch_bounds__(K1_THREADS, 2)
void k1_stream(const float* __restrict__ hidden)
{
    extern __shared__ __align__(128) unsigned char smem_raw[];
    float* s_tiles = (float*)(smem_raw + OFF_TILES);
    float* s_acc   = (float*)(smem_raw + OFF_ACC);
    float* s_wm    = (float*)(smem_raw + OFF_WM);
    float* s_wz    = (float*)(smem_raw + OFF_WZ);

    const int tid  = threadIdx.x;
    const int lane = tid & 31;

    const uint32_t full0  = s2u(smem_raw + OFF_BARS);
    const uint32_t empty0 = full0 + NSTAGE * 8;
    const uint32_t tile0  = s2u(smem_raw);

    if (tid == 0) {
        #pragma unroll
        for (int s = 0; s < NSTAGE; s++) {
            mbar_init(full0 + s * 8, 1);       // completed by copy tx
            mbar_init(empty0 + s * 8, NCONS);  // 4 consumer arrivals
        }
        fence_async_shared();
    }
    __syncthreads();
    // pre-arm: every empty barrier completes phase 0 -> producer's first
    // NSTAGE waits (parity 0) pass immediately
    if (tid < 128 && lane == 0) {
        #pragma unroll
        for (int s = 0; s < NSTAGE; s++) mbar_arrive(empty0 + s * 8);
    }
    __syncthreads();

    if (tid >= 128) {
        // ---------------- producer warp (lane 0 only) ----------------
        if (tid == PROD_TID) {
            int pos = 0, ph = 0;
            for (int id = blockIdx.x; id < NCHUNKS_TOTAL; id += K1_GRID) {
                const float* csrc = hidden
                    + ((size_t)(id >> 4) * TT + (id & 15) * CHUNK_ROWS) * HH;
                #pragma unroll
                for (int j = 0; j < STAGES_PER_CHUNK; j++) {
                    mbar_wait(empty0 + pos * 8, ph);
                    mbar_expect_tx(full0 + pos * 8, STAGE_BYTES);
                    bulk_copy_g2s(tile0 + pos * STAGE_BYTES,
                                  csrc + (size_t)j * STAGE_ROWS * HH,
                                  STAGE_BYTES, full0 + pos * 8);
                    if (++pos == NSTAGE) { pos = 0; ph ^= 1; }
                }
            }
        }
        return;
    }

    // ---------------- consumer warps (tid 0..127) ----------------
    const int cw = tid >> 5;             // 0..3, owns rows 4cw..4cw+3 of stage
    int pos = 0, ph = 0;

    for (int id = blockIdx.x; id < NCHUNKS_TOTAL; id += K1_GRID) {
        const int b = id >> 4;
        const float4 v0 = *(const float4*)(g_v + b * HH + lane * 4);
        const float4 v1 = *(const float4*)(g_v + b * HH + 128 + lane * 4);

        float  m = -CUDART_INF_F, Z = 0.f;
        float4 a0 = make_float4(0.f, 0.f, 0.f, 0.f);
        float4 a1 = make_float4(0.f, 0.f, 0.f, 0.f);

        for (int j = 0; j < STAGES_PER_CHUNK; j++) {
            mbar_wait(full0 + pos * 8, ph);

            const float* tp = s_tiles + pos * (STAGE_ROWS * HH) + cw * 4 * HH;
            float4 x[4][2];
            #pragma unroll
            for (int r = 0; r < 4; r++) {
                x[r][0] = *(const float4*)(tp + r * HH + lane * 4);
                x[r][1] = *(const float4*)(tp + r * HH + 128 + lane * 4);
            }
            float sc[4];
            #pragma unroll
            for (int r = 0; r < 4; r++) {
                sc[r] = x[r][0].x * v0.x + x[r][0].y * v0.y + x[r][0].z * v0.z + x[r][0].w * v0.w
                      + x[r][1].x * v1.x + x[r][1].y * v1.y + x[r][1].z * v1.z + x[r][1].w * v1.w;
            }
            // data now in registers -> free the stage for the producer
            __syncwarp();
            if (lane == 0) mbar_arrive(empty0 + pos * 8);

            #pragma unroll
            for (int off = 16; off; off >>= 1) {
                #pragma unroll
                for (int r = 0; r < 4; r++)
                    sc[r] += __shfl_xor_sync(0xffffffffu, sc[r], off);
            }
            const float mc = fmaxf(fmaxf(sc[0], sc[1]), fmaxf(sc[2], sc[3]));
            if (mc > m) {                         // warp-uniform
                const float rr = __expf(m - mc);  // first stage: exp(-inf)=0
                Z *= rr;
                a0.x *= rr; a0.y *= rr; a0.z *= rr; a0.w *= rr;
                a1.x *= rr; a1.y *= rr; a1.z *= rr; a1.w *= rr;
                m = mc;
            }
            #pragma unroll
            for (int r = 0; r < 4; r++) {
                const float p = __expf(sc[r] - m);
                Z += p;
                a0.x += p * x[r][0].x; a0.y += p * x[r][0].y;
                a0.z += p * x[r][0].z; a0.w += p * x[r][0].w;
                a1.x += p * x[r][1].x; a1.y += p * x[r][1].y;
                a1.z += p * x[r][1].z; a1.w += p * x[r][1].w;
            }
            if (++pos == NSTAGE) { pos = 0; ph ^= 1; }
        }

        // -------- per-chunk flush (4 consumer warps) --------
        if (lane == 0) { s_wm[cw] = m; s_wz[cw] = Z; }
        *(float4*)(&s_acc[cw * HH + lane * 4])       = a0;
        *(float4*)(&s_acc[cw * HH + 128 + lane * 4]) = a1;
        bar_cons();

        const float M = fmaxf(fmaxf(s_wm[0], s_wm[1]), fmaxf(s_wm[2], s_wm[3]));
        const float e0 = __expf(s_wm[0] - M), e1 = __expf(s_wm[1] - M);
        const float e2 = __expf(s_wm[2] - M), e3 = __expf(s_wm[3] - M);
        if (tid == 0) {
            g_m[id] = M;
            g_z[id] = e0 * s_wz[0] + e1 * s_wz[1] + e2 * s_wz[2] + e3 * s_wz[3];
        }
        #pragma unroll
        for (int jj = 0; jj < 2; jj++) {
            const int ch = tid + jj * 128;
            g_acc[(size_t)id * HH + ch] =
                e0 * s_acc[0 * HH + ch] + e1 * s_acc[1 * HH + ch]
              + e2 * s_acc[2 * HH + ch] + e3 * s_acc[3 * HH + ch];
        }
        bar_cons();   // protect s_wm/s_acc before next chunk's writes
    }
}

// ---------------------------------------------------------------------------
// kernel2: merge 16 partials/batch -> ctx; out = tanh(concat(ctx,ht) @ W_att)
//          grid = 16 CTAs x 8 batches, 512 thr, W_att staged through smem.
// ---------------------------------------------------------------------------
__global__ __launch_bounds__(512)
void k2_combine(const float* __restrict__ hidden,
                const float* __restrict__ Watt,
                float* __restrict__ out)
{
    __shared__ float s_pre[8][2 * HH];   // 16KB
    __shared__ float s_e[8][NCHUNK];     // 8 x 16
    __shared__ float s_Z[8];
    __shared__ float sW[32 * OUTD];      // 16KB W_att tile

    const int b0 = blockIdx.x * 8;
    const int tid = threadIdx.x;

    if (tid < 8 * NCHUNK) {              // stash m values
        const int bi = tid >> 4, p = tid & 15;
        s_e[bi][p] = g_m[(b0 + bi) * NCHUNK + p];
    }
    __syncthreads();
    if (tid < 8) {
        float M = -CUDART_INF_F;
        #pragma unroll
        for (int p = 0; p < NCHUNK; p++) M = fmaxf(M, s_e[tid][p]);
        float Zt = 0.f;
        #pragma unroll
        for (int p = 0; p < NCHUNK; p++) {
            const float e = __expf(s_e[tid][p] - M);
            Zt += e * g_z[(b0 + tid) * NCHUNK + p];
            s_e[tid][p] = e;
        }
        s_Z[tid] = Zt;
    }
    __syncthreads();

    const int bi = tid >> 6, c0 = tid & 63;
    #pragma unroll
    for (int cc = 0; cc < 4; cc++) {
        const int ch = c0 + cc * 64;
        float c = 0.f;
        #pragma unroll
        for (int p = 0; p < NCHUNK; p++)
            c += s_e[bi][p] * g_acc[(size_t)((b0 + bi) * NCHUNK + p) * HH + ch];
        s_pre[bi][ch]      = c / s_Z[bi];
        s_pre[bi][HH + ch] = hidden[((size_t)(b0 + bi) * TT + (TT - 1)) * HH + ch];
    }
    __syncthreads();

    // out[bi][j], 2 outputs/thread; W_att tiled 32 rows at a time via smem
    const int j = tid & 63;
    float acc0 = 0.f, acc1 = 0.f;
    for (int t = 0; t < 16; t++) {
        #pragma unroll
        for (int q = 0; q < 8; q++)
            sW[tid + q * 512] = Watt[(t * 32) * OUTD + tid + q * 512];
        __syncthreads();
        #pragma unroll
        for (int i = 0; i < 32; i++) {
            const float p = s_pre[bi][t * 32 + i];
            acc0 += p * sW[i * OUTD + j];
            acc1 += p * sW[i * OUTD + j + 64];
        }
        __syncthreads();
    }
    out[(b0 + bi) * OUTD + j]      = tanhf(acc0);
    out[(b0 + bi) * OUTD + j + 64] = tanhf(acc1);
}

extern "C" void kernel_launch(void* const* d_in, const int* in_sizes, int n_in,
                              void* d_out, int out_size) {
    const float* hidden = (const float*)d_in[0];   // (128, 2048, 256) f32
    const float* Wscore = (const float*)d_in[1];   // (256, 256) f32
    const float* Watt   = (const float*)d_in[2];   // (512, 128) f32
    float* out = (float*)d_out;                    // (128, 128) f32

    cudaFuncSetAttribute(k1_stream, cudaFuncAttributeMaxDynamicSharedMemorySize, SMEM_K1);

    k0_compute_v<<<dim3(BB / 8, HH / 8), 128>>>(hidden, Wscore);
    k1_stream<<<K1_GRID, K1_THREADS, SMEM_K1>>>(hidden);
    k2_combine<<<16, 512>>>(hidden, Watt, out);
}

// round 9
// speedup vs baseline: 1.0150x; 1.0150x over previous
#include <cuda_runtime.h>
#include <math_constants.h>
#include <cstdint>

#define BB 128
#define TT 2048
#define HH 256
#define OUTD 128

#define NCHUNK 8                          // chunks per batch
#define ROWS_PER_CTA (TT / NCHUNK)        // 256 rows
#define NPART (BB * NCHUNK)               // 1024

#define K1_THREADS 128                    // 4 warps
#define K1_WARPS 4
#define ROWS_PER_WARP (ROWS_PER_CTA / K1_WARPS)   // 64
#define STAGE_ROWS 4
#define STAGE_BYTES (STAGE_ROWS * HH * 4) // 4096
#define NSTAGE 4
#define ITERS (ROWS_PER_WARP / STAGE_ROWS) // 16

// dynamic smem layout (bytes)
#define OFF_TILES 0
#define SZ_TILES  (K1_WARPS * NSTAGE * STAGE_BYTES)    // 65536
#define OFF_ACC   (OFF_TILES + SZ_TILES)               // 65536
#define SZ_ACC    (K1_WARPS * HH * 4)                  // 4096
#define OFF_WM    (OFF_ACC + SZ_ACC)                   // 69632
#define OFF_WZ    (OFF_WM + 16)
#define OFF_BARS  (OFF_WZ + 16)                        // 69664 (8-aligned)
#define SMEM_K1   (OFF_BARS + K1_WARPS * NSTAGE * 8)   // 69792 -> 3 CTAs/SM

// Global scratch (allocation-free)
__device__ float g_v4[4 * BB * HH];       // split-K partials of v
__device__ float g_m[NPART];
__device__ float g_z[NPART];
__device__ float g_acc[NPART * HH];

// ---------------- PTX helpers ----------------
__device__ __forceinline__ uint32_t s2u(const void* p) {
    uint32_t a;
    asm("{ .reg .u64 t; cvta.to.shared.u64 t, %1; cvt.u32.u64 %0, t; }"
        : "=r"(a) : "l"(p));
    return a;
}
__device__ __forceinline__ void mbar_init(uint32_t bar, uint32_t cnt) {
    asm volatile("mbarrier.init.shared.b64 [%0], %1;" :: "r"(bar), "r"(cnt) : "memory");
}
__device__ __forceinline__ void mbar_expect_tx(uint32_t bar, uint32_t bytes) {
    asm volatile("mbarrier.arrive.expect_tx.shared.b64 _, [%0], %1;"
                 :: "r"(bar), "r"(bytes) : "memory");
}
__device__ __forceinline__ void mbar_wait(uint32_t bar, uint32_t parity) {
    uint32_t done;
    asm volatile(
        "{ .reg .pred p; mbarrier.try_wait.parity.acquire.cta.shared::cta.b64 p, [%1], %2; "
        "selp.b32 %0, 1, 0, p; }" : "=r"(done) : "r"(bar), "r"(parity) : "memory");
    while (!done) {
        asm volatile(
            "{ .reg .pred p; mbarrier.try_wait.parity.acquire.cta.shared::cta.b64 p, [%1], %2, 0x989680; "
            "selp.b32 %0, 1, 0, p; }" : "=r"(done) : "r"(bar), "r"(parity) : "memory");
    }
}
__device__ __forceinline__ void bulk_copy_g2s(uint32_t dst_smem, const void* src,
                                              uint32_t bytes, uint32_t mbar) {
    asm volatile(
        "cp.async.bulk.shared::cta.global.mbarrier::complete_tx::bytes [%0], [%1], %2, [%3];"
        :: "r"(dst_smem), "l"(src), "r"(bytes), "r"(mbar) : "memory");
}
__device__ __forceinline__ void fence_async_shared() {
    asm volatile("fence.proxy.async.shared::cta;" ::: "memory");
}

// ---------------------------------------------------------------------------
// kernel0: split-K partials  v4[q][b][h] = sum_{k in 64q..64q+63} W[h,k]*ht[b,k]
//          grid = (128 batches, 4 k-quarters) x 256 thr (8 warps x 32 h-rows)
// ---------------------------------------------------------------------------
__global__ __launch_bounds__(256)
void k0_compute_v(const float* __restrict__ hidden,
                  const float* __restrict__ Wscore)
{
    __shared__ float s_ht[64];
    const int b = blockIdx.x, q = blockIdx.y;
    const int tid = threadIdx.x, w = tid >> 5, lane = tid & 31;

    if (tid < 64)
        s_ht[tid] = hidden[((size_t)b * TT + (TT - 1)) * HH + q * 64 + tid];
    __syncthreads();

    const float c0 = s_ht[lane * 2];
    const float c1 = s_ht[lane * 2 + 1];

    const int h0 = w * 32;
    const float* wbase = Wscore + (size_t)h0 * HH + q * 64 + lane * 2;
    float* vout = g_v4 + ((size_t)q * BB + b) * HH + h0;

    #pragma unroll
    for (int rr = 0; rr < 8; rr++) {
        float2 wv[4];
        #pragma unroll
        for (int j = 0; j < 4; j++)
            wv[j] = *(const float2*)(wbase + (size_t)(rr * 4 + j) * HH);
        float s[4];
        #pragma unroll
        for (int j = 0; j < 4; j++) s[j] = wv[j].x * c0 + wv[j].y * c1;
        #pragma unroll
        for (int off = 16; off; off >>= 1) {
            #pragma unroll
            for (int j = 0; j < 4; j++)
                s[j] += __shfl_xor_sync(0xffffffffu, s[j], off);
        }
        const float val = (lane == 0) ? s[0] : (lane == 1) ? s[1]
                        : (lane == 2) ? s[2] : s[3];
        if (lane < 4) vout[rr * 4 + lane] = val;
    }
}

// ---------------------------------------------------------------------------
// kernel1: per-warp self-paced bulk-async pipeline (R5 config: 4 stages x 4KB,
//          occ 3). grid = BB*NCHUNK = 1024, 128 thr.
// ---------------------------------------------------------------------------
__global__ __launch_bounds__(K1_THREADS, 3)
void k1_stream(const float* __restrict__ hidden)
{
    extern __shared__ __align__(128) unsigned char smem_raw[];
    float* s_tiles = (float*)(smem_raw + OFF_TILES);
    float* s_acc   = (float*)(smem_raw + OFF_ACC);
    float* s_wm    = (float*)(smem_raw + OFF_WM);
    float* s_wz    = (float*)(smem_raw + OFF_WZ);

    const int cta   = blockIdx.x;
    const int b     = cta >> 3;               // / NCHUNK
    const int chunk = cta & (NCHUNK - 1);
    const int tid   = threadIdx.x, w = tid >> 5, lane = tid & 31;

    const uint32_t bar0  = s2u(smem_raw + OFF_BARS) + w * NSTAGE * 8;
    const uint32_t tile0 = s2u(smem_raw) + w * NSTAGE * STAGE_BYTES;
    float* tbase = s_tiles + w * NSTAGE * (STAGE_ROWS * HH);

    const float* src = hidden
        + ((size_t)b * TT + chunk * ROWS_PER_CTA + w * ROWS_PER_WARP) * HH;

    // per-warp barrier init + prologue copies (no cross-warp sync needed)
    if (lane == 0) {
        #pragma unroll
        for (int s = 0; s < NSTAGE; s++) mbar_init(bar0 + s * 8, 1);
        fence_async_shared();
        #pragma unroll
        for (int s = 0; s < NSTAGE; s++) {
            mbar_expect_tx(bar0 + s * 8, STAGE_BYTES);
            bulk_copy_g2s(tile0 + s * STAGE_BYTES,
                          src + (size_t)s * STAGE_ROWS * HH,
                          STAGE_BYTES, bar0 + s * 8);
        }
    }
    __syncwarp();

    // per-lane v slice: sum the 4 split-K partials (L2-hot, trivial)
    float4 v0, v1;
    {
        const float* p0 = g_v4 + (size_t)b * HH;
        float4 t0 = *(const float4*)(p0 + lane * 4);
        float4 t1 = *(const float4*)(p0 + 128 + lane * 4);
        #pragma unroll
        for (int qq = 1; qq < 4; qq++) {
            const float* pq = g_v4 + ((size_t)qq * BB + b) * HH;
            const float4 u0 = *(const float4*)(pq + lane * 4);
            const float4 u1 = *(const float4*)(pq + 128 + lane * 4);
            t0.x += u0.x; t0.y += u0.y; t0.z += u0.z; t0.w += u0.w;
            t1.x += u1.x; t1.y += u1.y; t1.z += u1.z; t1.w += u1.w;
        }
        v0 = t0; v1 = t1;
    }

    float  m = -CUDART_INF_F, Z = 0.f;
    float4 a0 = make_float4(0.f, 0.f, 0.f, 0.f);
    float4 a1 = make_float4(0.f, 0.f, 0.f, 0.f);

    for (int i = 0; i < ITERS; i++) {
        const int s = i & (NSTAGE - 1);
        mbar_wait(bar0 + s * 8, (i >> 2) & 1);

        const float* tp = tbase + s * (STAGE_ROWS * HH);
        float4 x[STAGE_ROWS][2];
        #pragma unroll
        for (int r = 0; r < STAGE_ROWS; r++) {
            x[r][0] = *(const float4*)(tp + r * HH + lane * 4);
            x[r][1] = *(const float4*)(tp + r * HH + 128 + lane * 4);
        }

        // consume the registers first (score FMAs)...
        float sc[STAGE_ROWS];
        #pragma unroll
        for (int r = 0; r < STAGE_ROWS; r++) {
            sc[r] = x[r][0].x * v0.x + x[r][0].y * v0.y + x[r][0].z * v0.z + x[r][0].w * v0.w
                  + x[r][1].x * v1.x + x[r][1].y * v1.y + x[r][1].z * v1.z + x[r][1].w * v1.w;
        }

        // ...then refill stage s (all lanes' LDS done per __syncwarp)
        __syncwarp();
        if (lane == 0 && i + NSTAGE < ITERS) {
            mbar_expect_tx(bar0 + s * 8, STAGE_BYTES);
            bulk_copy_g2s(tile0 + s * STAGE_BYTES,
                          src + (size_t)(i + NSTAGE) * STAGE_ROWS * HH,
                          STAGE_BYTES, bar0 + s * 8);
        }

        #pragma unroll
        for (int off = 16; off; off >>= 1) {
            #pragma unroll
            for (int r = 0; r < STAGE_ROWS; r++)
                sc[r] += __shfl_xor_sync(0xffffffffu, sc[r], off);
        }
        const float mc = fmaxf(fmaxf(sc[0], sc[1]), fmaxf(sc[2], sc[3]));
        if (mc > m) {                          // warp-uniform
            const float rr = __expf(m - mc);   // first stage: exp(-inf)=0
            Z *= rr;
            a0.x *= rr; a0.y *= rr; a0.z *= rr; a0.w *= rr;
            a1.x *= rr; a1.y *= rr; a1.z *= rr; a1.w *= rr;
            m = mc;
        }
        #pragma unroll
        for (int r = 0; r < STAGE_ROWS; r++) {
            const float p = __expf(sc[r] - m);
            Z += p;
            a0.x += p * x[r][0].x; a0.y += p * x[r][0].y;
            a0.z += p * x[r][0].z; a0.w += p * x[r][0].w;
            a1.x += p * x[r][1].x; a1.y += p * x[r][1].y;
            a1.z += p * x[r][1].z; a1.w += p * x[r][1].w;
        }
    }

    // intra-CTA combine (4 warps)
    if (lane == 0) { s_wm[w] = m; s_wz[w] = Z; }
    *(float4*)(&s_acc[w * HH + lane * 4])       = a0;
    *(float4*)(&s_acc[w * HH + 128 + lane * 4]) = a1;
    __syncthreads();

    const float M = fmaxf(fmaxf(s_wm[0], s_wm[1]), fmaxf(s_wm[2], s_wm[3]));
    const float e0 = __expf(s_wm[0] - M), e1 = __expf(s_wm[1] - M);
    const float e2 = __expf(s_wm[2] - M), e3 = __expf(s_wm[3] - M);

    if (tid == 0) {
        g_m[cta] = M;
        g_z[cta] = e0 * s_wz[0] + e1 * s_wz[1] + e2 * s_wz[2] + e3 * s_wz[3];
    }
    #pragma unroll
    for (int jj = 0; jj < 2; jj++) {
        const int ch = tid + jj * 128;
        g_acc[(size_t)cta * HH + ch] =
            e0 * s_acc[0 * HH + ch] + e1 * s_acc[1 * HH + ch]
          + e2 * s_acc[2 * HH + ch] + e3 * s_acc[3 * HH + ch];
    }
}

// ---------------------------------------------------------------------------
// kernel2: merge partials -> ctx; out = tanh(concat(ctx,h_t) @ W_att).
//          grid = 16 CTAs x 8 batches, 512 thr, W_att staged through smem.
// ---------------------------------------------------------------------------
__global__ __launch_bounds__(512)
void k2_combine(const float* __restrict__ hidden,
                const float* __restrict__ Watt,
                float* __restrict__ out)
{
    __shared__ float s_pre[8][2 * HH];   // 16KB
    __shared__ float s_e[8][NCHUNK];
    __shared__ float s_Z[8];
    __shared__ float sW[32 * OUTD];      // 16KB W_att tile

    const int b0 = blockIdx.x * 8;
    const int tid = threadIdx.x;

    if (tid < 8 * NCHUNK) {              // stash m values
        const int bi = tid >> 3, p = tid & 7;
        s_e[bi][p] = g_m[(b0 + bi) * NCHUNK + p];
    }
    __syncthreads();
    if (tid < 8) {
        float M = -CUDART_INF_F;
        #pragma unroll
        for (int p = 0; p < NCHUNK; p++) M = fmaxf(M, s_e[tid][p]);
        float Zt = 0.f;
        #pragma unroll
        for (int p = 0; p < NCHUNK; p++) {
            const float e = __expf(s_e[tid][p] - M);
            Zt += e * g_z[(b0 + tid) * NCHUNK + p];
            s_e[tid][p] = e;
        }
        s_Z[tid] = Zt;
    }
    __syncthreads();

    const int bi = tid >> 6, c0 = tid & 63;
    #pragma unroll
    for (int cc = 0; cc < 4; cc++) {
        const int ch = c0 + cc * 64;
        float c = 0.f;
        #pragma unroll
        for (int p = 0; p < NCHUNK; p++)
            c += s_e[bi][p] * g_acc[(size_t)((b0 + bi) * NCHUNK + p) * HH + ch];
        s_pre[bi][ch]      = c / s_Z[bi];
        s_pre[bi][HH + ch] = hidden[((size_t)(b0 + bi) * TT + (TT - 1)) * HH + ch];
    }
    __syncthreads();

    // out[bi][j], 2 outputs per thread; W_att tiled 32 rows at a time via smem
    const int j = tid & 63;
    float acc0 = 0.f, acc1 = 0.f;
    for (int t = 0; t < 16; t++) {
        #pragma unroll
        for (int q = 0; q < 8; q++)      // 512 thr load 32x128 = 4096 floats
            sW[tid + q * 512] = Watt[(t * 32) * OUTD + tid + q * 512];
        __syncthreads();
        #pragma unroll
        for (int i = 0; i < 32; i++) {
            const float p = s_pre[bi][t * 32 + i];
            acc0 += p * sW[i * OUTD + j];
            acc1 += p * sW[i * OUTD + j + 64];
        }
        __syncthreads();
    }
    out[(b0 + bi) * OUTD + j]      = tanhf(acc0);
    out[(b0 + bi) * OUTD + j + 64] = tanhf(acc1);
}

extern "C" void kernel_launch(void* const* d_in, const int* in_sizes, int n_in,
                              void* d_out, int out_size) {
    const float* hidden = (const float*)d_in[0];   // (128, 2048, 256) f32
    const float* Wscore = (const float*)d_in[1];   // (256, 256) f32
    const float* Watt   = (const float*)d_in[2];   // (512, 128) f32
    float* out = (float*)d_out;                    // (128, 128) f32

    cudaFuncSetAttribute(k1_stream, cudaFuncAttributeMaxDynamicSharedMemorySize, SMEM_K1);

    k0_compute_v<<<dim3(BB, 4), 256>>>(hidden, Wscore);
    k1_stream<<<BB * NCHUNK, K1_THREADS, SMEM_K1>>>(hidden);
    k2_combine<<<16, 512>>>(hidden, Watt, out);
}

// round 11
// speedup vs baseline: 1.1364x; 1.1196x over previous
#include <cuda_runtime.h>
#include <math_constants.h>
#include <cstdint>

#define BB 128
#define TT 2048
#define HH 256
#define OUTD 128

#define NCHUNK 8                          // chunks per batch
#define ROWS_PER_CTA (TT / NCHUNK)        // 256 rows
#define NPART (BB * NCHUNK)               // 1024

#define K1_THREADS 128                    // 4 warps
#define K1_WARPS 4
#define ROWS_PER_WARP (ROWS_PER_CTA / K1_WARPS)   // 64
#define STAGE_ROWS 4
#define STAGE_BYTES (STAGE_ROWS * HH * 4) // 4096
#define NSTAGE 4
#define ITERS (ROWS_PER_WARP / STAGE_ROWS) // 16

// dynamic smem layout (bytes)
#define OFF_TILES 0
#define SZ_TILES  (K1_WARPS * NSTAGE * STAGE_BYTES)    // 65536
#define OFF_ACC   (OFF_TILES + SZ_TILES)               // 65536
#define SZ_ACC    (K1_WARPS * HH * 4)                  // 4096
#define OFF_WM    (OFF_ACC + SZ_ACC)                   // 69632
#define OFF_WZ    (OFF_WM + 16)
#define OFF_BARS  (OFF_WZ + 16)                        // 69664 (8-aligned)
#define SMEM_K1   (OFF_BARS + K1_WARPS * NSTAGE * 8)   // 69792 -> 3 CTAs/SM

// Global scratch (allocation-free)
__device__ float g_v[BB * HH];
__device__ float g_m[NPART];
__device__ float g_z[NPART];
__device__ float g_acc[NPART * HH];

// ---------------- PTX helpers ----------------
__device__ __forceinline__ uint32_t s2u(const void* p) {
    uint32_t a;
    asm("{ .reg .u64 t; cvta.to.shared.u64 t, %1; cvt.u32.u64 %0, t; }"
        : "=r"(a) : "l"(p));
    return a;
}
__device__ __forceinline__ void mbar_init(uint32_t bar, uint32_t cnt) {
    asm volatile("mbarrier.init.shared.b64 [%0], %1;" :: "r"(bar), "r"(cnt) : "memory");
}
__device__ __forceinline__ void mbar_expect_tx(uint32_t bar, uint32_t bytes) {
    asm volatile("mbarrier.arrive.expect_tx.shared.b64 _, [%0], %1;"
                 :: "r"(bar), "r"(bytes) : "memory");
}
__device__ __forceinline__ void mbar_wait(uint32_t bar, uint32_t parity) {
    uint32_t done;
    asm volatile(
        "{ .reg .pred p; mbarrier.try_wait.parity.acquire.cta.shared::cta.b64 p, [%1], %2; "
        "selp.b32 %0, 1, 0, p; }" : "=r"(done) : "r"(bar), "r"(parity) : "memory");
    while (!done) {
        asm volatile(
            "{ .reg .pred p; mbarrier.try_wait.parity.acquire.cta.shared::cta.b64 p, [%1], %2, 0x989680; "
            "selp.b32 %0, 1, 0, p; }" : "=r"(done) : "r"(bar), "r"(parity) : "memory");
    }
}
__device__ __forceinline__ void bulk_copy_g2s(uint32_t dst_smem, const void* src,
                                              uint32_t bytes, uint32_t mbar) {
    asm volatile(
        "cp.async.bulk.shared::cta.global.mbarrier::complete_tx::bytes [%0], [%1], %2, [%3];"
        :: "r"(dst_smem), "l"(src), "r"(bytes), "r"(mbar) : "memory");
}
__device__ __forceinline__ void fence_async_shared() {
    asm volatile("fence.proxy.async.shared::cta;" ::: "memory");
}
__device__ __forceinline__ void pdl_wait() {
    asm volatile("griddepcontrol.wait;" ::: "memory");
}
__device__ __forceinline__ void pdl_launch_dependents() {
    asm volatile("griddepcontrol.launch_dependents;" ::: "memory");
}

// ---------------------------------------------------------------------------
// kernel0: V[b,h] = sum_k W_score[h,k]*ht[b,k]
//   grid = (16 b-groups x 16 h-groups) = 256 CTAs, 256 thr.
//   Warp w: 2 W-rows in registers, 8 ht rows in smem -> 16 independent
//   dot+shuffle chains, no serial reloads. ~1.5k cyc/CTA, <2 waves.
// ---------------------------------------------------------------------------
__global__ __launch_bounds__(256)
void k0_compute_v(const float* __restrict__ hidden,
                  const float* __restrict__ Wscore)
{
    __shared__ float s_ht[8][HH];
    const int b0 = blockIdx.x * 8;
    const int h0 = blockIdx.y * 16;
    const int tid = threadIdx.x, w = tid >> 5, lane = tid & 31;

    // warp w loads ht row for batch b0+w
    {
        const float* hp = hidden + ((size_t)(b0 + w) * TT + (TT - 1)) * HH;
        *(float4*)&s_ht[w][lane * 4]       = *(const float4*)(hp + lane * 4);
        *(float4*)&s_ht[w][128 + lane * 4] = *(const float4*)(hp + 128 + lane * 4);
    }
    // W rows h0+2w, h0+2w+1 in registers (lane's 8 channels)
    const int h = h0 + w * 2;
    const float* w0p = Wscore + (size_t)h * HH;
    const float4 wa0 = *(const float4*)(w0p + lane * 4);
    const float4 wa1 = *(const float4*)(w0p + 128 + lane * 4);
    const float4 wb0 = *(const float4*)(w0p + HH + lane * 4);
    const float4 wb1 = *(const float4*)(w0p + HH + 128 + lane * 4);
    __syncthreads();

    float o0 = 0.f, o1 = 0.f;
    #pragma unroll
    for (int b = 0; b < 8; b++) {
        const float4 x0 = *(const float4*)&s_ht[b][lane * 4];
        const float4 x1 = *(const float4*)&s_ht[b][128 + lane * 4];
        float s0 = wa0.x * x0.x + wa0.y * x0.y + wa0.z * x0.z + wa0.w * x0.w
                 + wa1.x * x1.x + wa1.y * x1.y + wa1.z * x1.z + wa1.w * x1.w;
        float s1 = wb0.x * x0.x + wb0.y * x0.y + wb0.z * x0.z + wb0.w * x0.w
                 + wb1.x * x1.x + wb1.y * x1.y + wb1.z * x1.z + wb1.w * x1.w;
        #pragma unroll
        for (int off = 16; off; off >>= 1) {
            s0 += __shfl_xor_sync(0xffffffffu, s0, off);
            s1 += __shfl_xor_sync(0xffffffffu, s1, off);
        }
        if (lane == b) { o0 = s0; o1 = s1; }   // compile-time b -> no spill
    }
    if (lane < 8) {
        g_v[(b0 + lane) * HH + h]     = o0;
        g_v[(b0 + lane) * HH + h + 1] = o1;
    }
    pdl_launch_dependents();
}

// ---------------------------------------------------------------------------
// kernel1: per-warp self-paced bulk-async pipeline (R5 config: 4 stages x 4KB,
//          occ 3). grid = BB*NCHUNK = 1024, 128 thr. PDL: prologue copies of
//          hidden overlap with k0; wait only before reading g_v.
// ---------------------------------------------------------------------------
__global__ __launch_bounds__(K1_THREADS, 3)
void k1_stream(const float* __restrict__ hidden)
{
    extern __shared__ __align__(128) unsigned char smem_raw[];
    float* s_tiles = (float*)(smem_raw + OFF_TILES);
    float* s_acc   = (float*)(smem_raw + OFF_ACC);
    float* s_wm    = (float*)(smem_raw + OFF_WM);
    float* s_wz    = (float*)(smem_raw + OFF_WZ);

    const int cta   = blockIdx.x;
    const int b     = cta >> 3;               // / NCHUNK
    const int chunk = cta & (NCHUNK - 1);
    const int tid   = threadIdx.x, w = tid >> 5, lane = tid & 31;

    const uint32_t bar0  = s2u(smem_raw + OFF_BARS) + w * NSTAGE * 8;
    const uint32_t tile0 = s2u(smem_raw) + w * NSTAGE * STAGE_BYTES;
    float* tbase = s_tiles + w * NSTAGE * (STAGE_ROWS * HH);

    const float* src = hidden
        + ((size_t)b * TT + chunk * ROWS_PER_CTA + w * ROWS_PER_WARP) * HH;

    // per-warp barrier init + prologue copies (independent of g_v -> overlaps k0)
    if (lane == 0) {
        #pragma unroll
        for (int s = 0; s < NSTAGE; s++) mbar_init(bar0 + s * 8, 1);
        fence_async_shared();
        #pragma unroll
        for (int s = 0; s < NSTAGE; s++) {
            mbar_expect_tx(bar0 + s * 8, STAGE_BYTES);
            bulk_copy_g2s(tile0 + s * STAGE_BYTES,
                          src + (size_t)s * STAGE_ROWS * HH,
                          STAGE_BYTES, bar0 + s * 8);
        }
    }
    __syncwarp();

    // PDL: g_v produced by k0 -- wait here, after the copies are in flight
    pdl_wait();

    const float4 v0 = *(const float4*)(g_v + b * HH + lane * 4);
    const float4 v1 = *(const float4*)(g_v + b * HH + 128 + lane * 4);

    float  m = -CUDART_INF_F, Z = 0.f;
    float4 a0 = make_float4(0.f, 0.f, 0.f, 0.f);
    float4 a1 = make_float4(0.f, 0.f, 0.f, 0.f);

    for (int i = 0; i < ITERS; i++) {
        const int s = i & (NSTAGE - 1);
        mbar_wait(bar0 + s * 8, (i >> 2) & 1);

        const float* tp = tbase + s * (STAGE_ROWS * HH);
        float4 x[STAGE_ROWS][2];
        #pragma unroll
        for (int r = 0; r < STAGE_ROWS; r++) {
            x[r][0] = *(const float4*)(tp + r * HH + lane * 4);
            x[r][1] = *(const float4*)(tp + r * HH + 128 + lane * 4);
        }

        // consume the registers first (score FMAs)...
        float sc[STAGE_ROWS];
        #pragma unroll
        for (int r = 0; r < STAGE_ROWS; r++) {
            sc[r] = x[r][0].x * v0.x + x[r][0].y * v0.y + x[r][0].z * v0.z + x[r][0].w * v0.w
                  + x[r][1].x * v1.x + x[r][1].y * v1.y + x[r][1].z * v1.z + x[r][1].w * v1.w;
        }

        // ...then refill stage s (all lanes' LDS done per __syncwarp)
        __syncwarp();
        if (lane == 0 && i + NSTAGE < ITERS) {
            mbar_expect_tx(bar0 + s * 8, STAGE_BYTES);
            bulk_copy_g2s(tile0 + s * STAGE_BYTES,
                          src + (size_t)(i + NSTAGE) * STAGE_ROWS * HH,
                          STAGE_BYTES, bar0 + s * 8);
        }

        #pragma unroll
        for (int off = 16; off; off >>= 1) {
            #pragma unroll
            for (int r = 0; r < STAGE_ROWS; r++)
                sc[r] += __shfl_xor_sync(0xffffffffu, sc[r], off);
        }
        const float mc = fmaxf(fmaxf(sc[0], sc[1]), fmaxf(sc[2], sc[3]));
        if (mc > m) {                          // warp-uniform
            const float rr = __expf(m - mc);   // first stage: exp(-inf)=0
            Z *= rr;
            a0.x *= rr; a0.y *= rr; a0.z *= rr; a0.w *= rr;
            a1.x *= rr; a1.y *= rr; a1.z *= rr; a1.w *= rr;
            m = mc;
        }
        #pragma unroll
        for (int r = 0; r < STAGE_ROWS; r++) {
            const float p = __expf(sc[r] - m);
            Z += p;
            a0.x += p * x[r][0].x; a0.y += p * x[r][0].y;
            a0.z += p * x[r][0].z; a0.w += p * x[r][0].w;
            a1.x += p * x[r][1].x; a1.y += p * x[r][1].y;
            a1.z += p * x[r][1].z; a1.w += p * x[r][1].w;
        }
    }

    // intra-CTA combine (4 warps)
    if (lane == 0) { s_wm[w] = m; s_wz[w] = Z; }
    *(float4*)(&s_acc[w * HH + lane * 4])       = a0;
    *(float4*)(&s_acc[w * HH + 128 + lane * 4]) = a1;
    __syncthreads();

    const float M = fmaxf(fmaxf(s_wm[0], s_wm[1]), fmaxf(s_wm[2], s_wm[3]));
    const float e0 = __expf(s_wm[0] - M), e1 = __expf(s_wm[1] - M);
    const float e2 = __expf(s_wm[2] - M), e3 = __expf(s_wm[3] - M);

    if (tid == 0) {
        g_m[cta] = M;
        g_z[cta] = e0 * s_wz[0] + e1 * s_wz[1] + e2 * s_wz[2] + e3 * s_wz[3];
    }
    #pragma unroll
    for (int jj = 0; jj < 2; jj++) {
        const int ch = tid + jj * 128;
        g_acc[(size_t)cta * HH + ch] =
            e0 * s_acc[0 * HH + ch] + e1 * s_acc[1 * HH + ch]
          + e2 * s_acc[2 * HH + ch] + e3 * s_acc[3 * HH + ch];
    }
    pdl_launch_dependents();
}

// ---------------------------------------------------------------------------
// kernel2: merge partials -> ctx; out = tanh(concat(ctx,h_t) @ W_att).
//          grid = 16 CTAs x 8 batches, 512 thr, W_att staged through smem.
// ---------------------------------------------------------------------------
__global__ __launch_bounds__(512)
void k2_combine(const float* __restrict__ hidden,
                const float* __restrict__ Watt,
                float* __restrict__ out)
{
    __shared__ float s_pre[8][2 * HH];   // 16KB
    __shared__ float s_e[8][NCHUNK];
    __shared__ float s_Z[8];
    __shared__ float sW[32 * OUTD];      // 16KB W_att tile

    const int b0 = blockIdx.x * 8;
    const int tid = threadIdx.x;

    pdl_wait();                          // k1 partials must be complete

    if (tid < 8 * NCHUNK) {              // stash m values
        const int bi = tid >> 3, p = tid & 7;
        s_e[bi][p] = g_m[(b0 + bi) * NCHUNK + p];
    }
    __syncthreads();
    if (tid < 8) {
        float M = -CUDART_INF_F;
        #pragma unroll
        for (int p = 0; p < NCHUNK; p++) M = fmaxf(M, s_e[tid][p]);
        float Zt = 0.f;
        #pragma unroll
        for (int p = 0; p < NCHUNK; p++) {
            const float e = __expf(s_e[tid][p] - M);
            Zt += e * g_z[(b0 + tid) * NCHUNK + p];
            s_e[tid][p] = e;
        }
        s_Z[tid] = Zt;
    }
    __syncthreads();

    const int bi = tid >> 6, c0 = tid & 63;
    #pragma unroll
    for (int cc = 0; cc < 4; cc++) {
        const int ch = c0 + cc * 64;
        float c = 0.f;
        #pragma unroll
        for (int p = 0; p < NCHUNK; p++)
            c += s_e[bi][p] * g_acc[(size_t)((b0 + bi) * NCHUNK + p) * HH + ch];
        s_pre[bi][ch]      = c / s_Z[bi];
        s_pre[bi][HH + ch] = hidden[((size_t)(b0 + bi) * TT + (TT - 1)) * HH + ch];
    }
    __syncthreads();

    // out[bi][j], 2 outputs per thread; W_att tiled 32 rows at a time via smem
    const int j = tid & 63;
    float acc0 = 0.f, acc1 = 0.f;
    for (int t = 0; t < 16; t++) {
        #pragma unroll
        for (int q = 0; q < 8; q++)      // 512 thr load 32x128 = 4096 floats
            sW[tid + q * 512] = Watt[(t * 32) * OUTD + tid + q * 512];
        __syncthreads();
        #pragma unroll
        for (int i = 0; i < 32; i++) {
            const float p = s_pre[bi][t * 32 + i];
            acc0 += p * sW[i * OUTD + j];
            acc1 += p * sW[i * OUTD + j + 64];
        }
        __syncthreads();
    }
    out[(b0 + bi) * OUTD + j]      = tanhf(acc0);
    out[(b0 + bi) * OUTD + j + 64] = tanhf(acc1);
}

extern "C" void kernel_launch(void* const* d_in, const int* in_sizes, int n_in,
                              void* d_out, int out_size) {
    const float* hidden = (const float*)d_in[0];   // (128, 2048, 256) f32
    const float* Wscore = (const float*)d_in[1];   // (256, 256) f32
    const float* Watt   = (const float*)d_in[2];   // (512, 128) f32
    float* out = (float*)d_out;                    // (128, 128) f32

    cudaFuncSetAttribute(k1_stream, cudaFuncAttributeMaxDynamicSharedMemorySize, SMEM_K1);

    k0_compute_v<<<dim3(BB / 8, HH / 16), 256>>>(hidden, Wscore);

    cudaLaunchAttribute pdl_attr;
    pdl_attr.id = cudaLaunchAttributeProgrammaticStreamSerialization;
    pdl_attr.val.programmaticStreamSerializationAllowed = 1;

    {   // k1 with PDL
        cudaLaunchConfig_t cfg = {};
        cfg.gridDim = dim3(BB * NCHUNK);
        cfg.blockDim = dim3(K1_THREADS);
        cfg.dynamicSmemBytes = SMEM_K1;
        cfg.stream = 0;
        cfg.attrs = &pdl_attr;
        cfg.numAttrs = 1;
        cudaLaunchKernelEx(&cfg, k1_stream, hidden);
    }
    {   // k2 with PDL
        cudaLaunchConfig_t cfg = {};
        cfg.gridDim = dim3(16);
        cfg.blockDim = dim3(512);
        cfg.dynamicSmemBytes = 0;
        cfg.stream = 0;
        cfg.attrs = &pdl_attr;
        cfg.numAttrs = 1;
        cudaLaunchKernelEx(&cfg, k2_combine, hidden, Watt, out);
    }
}